// round 3
// baseline (speedup 1.0000x reference)
#include <cuda_runtime.h>
#include <stdint.h>

// GINGCN forward:
//   deg[c]  = # edges with col==c
//   dis[i]  = deg[i]>0 ? rsqrt(deg[i]) : 0
//   out[r]  = (1+eps)*x[r] + sum_{e: row[e]==r} dis[r]*dis[col[e]] * x[col[e]]
//
// Strategy: bucket-CSR gather (avoids 204.8M float atomics).
//   K0 zero counters
//   K1 detect edge_index dtype (int64 vs int32)
//   K2 count in-degree over col (int atomics)
//   K3 dis[i]
//   K4 out = (1+eps)*x   (vectorized float4)
//   K5 fill per-row buckets (col, norm packed as int2) with int atomics;
//      overflow -> float atomics straight into out (P ~ 1e-18/node at mean
//      degree 16, but keeps correctness unconditional)
//   K6 gather: 1 warp per node, lane owns 4 features; bucket entries loaded
//      cooperatively and broadcast via shfl; x row gathered as float4
//      (512B/warp/edge, coalesced, L2-resident).

#define N_MAX 100000
#define D     128
#define D4    (D / 4)      // 32 float4 per row
#define CAP   64

__device__ int   g_deg[N_MAX];                  // in-degree (col counts)
__device__ int   g_cnt[N_MAX];                  // per-row bucket fill counts
__device__ float g_dis[N_MAX];                  // deg^{-1/2}
__device__ int2  g_bkt[(size_t)N_MAX * CAP];    // bucket: {col, norm-bits}
__device__ int   g_is64;                        // edge dtype flag

// ---------------------------------------------------------------- edge access
__device__ __forceinline__ int edge_val(const void* ei, size_t idx, int is64) {
    if (is64) return (int)((const long long*)ei)[idx];
    return ((const int*)ei)[idx];
}

// ---------------------------------------------------------------- K0: zero
__global__ void k_zero(int n) {
    int i = blockIdx.x * blockDim.x + threadIdx.x;
    if (i < n) { g_deg[i] = 0; g_cnt[i] = 0; }
}

// ---------------------------------------------------------------- K1: detect
// int64 little-endian values < 2^31 -> every odd int32 word is 0.
// 64 odd words all zero from genuine int32 node-id data is ~impossible.
__global__ void k_detect(const void* ei) {
    if (threadIdx.x == 0 && blockIdx.x == 0) {
        const int* p = (const int*)ei;
        int nz = 0;
        #pragma unroll
        for (int k = 0; k < 64; k++) nz |= p[2 * k + 1];
        g_is64 = (nz == 0) ? 1 : 0;
    }
}

// ---------------------------------------------------------------- K2: degree
__global__ void k_count(const void* ei, int E) {
    int e = blockIdx.x * blockDim.x + threadIdx.x;
    if (e >= E) return;
    int is64 = g_is64;
    int c = edge_val(ei, (size_t)E + e, is64);
    atomicAdd(&g_deg[c], 1);
}

// ---------------------------------------------------------------- K3: dis
__global__ void k_dis(int n) {
    int i = blockIdx.x * blockDim.x + threadIdx.x;
    if (i >= n) return;
    int d = g_deg[i];
    g_dis[i] = (d > 0) ? rsqrtf((float)d) : 0.0f;
}

// ---------------------------------------------------------------- K4: init out
__global__ void k_init_out(const float4* __restrict__ x4,
                           float4* __restrict__ o4,
                           const float* __restrict__ eps, int n4) {
    int i = blockIdx.x * blockDim.x + threadIdx.x;
    if (i >= n4) return;
    float s = 1.0f + eps[0];
    float4 v = x4[i];
    v.x *= s; v.y *= s; v.z *= s; v.w *= s;
    o4[i] = v;
}

// ---------------------------------------------------------------- K5: fill
__global__ void k_fill(const void* ei, int E,
                       const float* __restrict__ x,
                       float* out) {
    int e = blockIdx.x * blockDim.x + threadIdx.x;
    if (e >= E) return;
    int is64 = g_is64;
    int r = edge_val(ei, (size_t)e, is64);
    int c = edge_val(ei, (size_t)E + e, is64);
    float norm = g_dis[r] * g_dis[c];
    int slot = atomicAdd(&g_cnt[r], 1);
    if (slot < CAP) {
        g_bkt[(size_t)r * CAP + slot] = make_int2(c, __float_as_int(norm));
    } else {
        // overflow fallback: direct atomic accumulate (essentially never taken)
        const float* xr = x + (size_t)c * D;
        float*       o  = out + (size_t)r * D;
        for (int j = 0; j < D; j++) atomicAdd(&o[j], norm * xr[j]);
    }
}

// ---------------------------------------------------------------- K6: gather
__global__ void __launch_bounds__(256)
k_gather(const float4* __restrict__ x4, float4* __restrict__ o4, int n) {
    int w    = (blockIdx.x * blockDim.x + threadIdx.x) >> 5;
    int lane = threadIdx.x & 31;
    if (w >= n) return;

    int cnt = g_cnt[w];
    if (cnt > CAP) cnt = CAP;

    float4 acc = o4[(size_t)w * D4 + lane];   // (1+eps)*x already there
    size_t base = (size_t)w * CAP;

    for (int j0 = 0; j0 < cnt; j0 += 32) {
        int2 mine = make_int2(0, 0);
        int idx = j0 + lane;
        if (idx < cnt) mine = g_bkt[base + idx];
        int m = min(32, cnt - j0);

        if (m == 32) {
            #pragma unroll 4
            for (int j = 0; j < 32; j++) {
                int   c  = __shfl_sync(0xffffffffu, mine.x, j);
                float nm = __int_as_float(__shfl_sync(0xffffffffu, mine.y, j));
                float4 v = x4[(size_t)c * D4 + lane];
                acc.x += nm * v.x;
                acc.y += nm * v.y;
                acc.z += nm * v.z;
                acc.w += nm * v.w;
            }
        } else {
            for (int j = 0; j < m; j++) {
                int   c  = __shfl_sync(0xffffffffu, mine.x, j);
                float nm = __int_as_float(__shfl_sync(0xffffffffu, mine.y, j));
                float4 v = x4[(size_t)c * D4 + lane];
                acc.x += nm * v.x;
                acc.y += nm * v.y;
                acc.z += nm * v.z;
                acc.w += nm * v.w;
            }
        }
    }
    o4[(size_t)w * D4 + lane] = acc;
}

// ---------------------------------------------------------------- launch
extern "C" void kernel_launch(void* const* d_in, const int* in_sizes, int n_in,
                              void* d_out, int out_size) {
    const float* x   = (const float*)d_in[0];
    const float* eps = (const float*)d_in[1];
    const void*  ei  = d_in[2];
    float*       out = (float*)d_out;

    int n = in_sizes[0] / D;       // 100000
    int E = in_sizes[2] / 2;       // 1600000
    int n4 = n * D4;               // float4 count of x/out

    const int T = 256;
    k_zero    <<<(n  + T - 1) / T, T>>>(n);
    k_detect  <<<1, 32>>>(ei);
    k_count   <<<(E  + T - 1) / T, T>>>(ei, E);
    k_dis     <<<(n  + T - 1) / T, T>>>(n);
    k_init_out<<<(n4 + T - 1) / T, T>>>((const float4*)x, (float4*)out, eps, n4);
    k_fill    <<<(E  + T - 1) / T, T>>>(ei, E, x, out);
    k_gather  <<<(n * 32 + T - 1) / T, T>>>((const float4*)x, (float4*)out, n);
}

// round 4
// speedup vs baseline: 1.2768x; 1.2768x over previous
#include <cuda_runtime.h>
#include <stdint.h>

// GINGCN forward:
//   deg[c]  = # edges with col==c
//   dis[i]  = deg[i]>0 ? rsqrt(deg[i]) : 0
//   out[r]  = (1+eps)*x[r] + sum_{e: row[e]==r} dis[r]*dis[col[e]] * x[col[e]]
//
// Strategy: bucket-CSR gather.
//   K0 zero counters + overflow count
//   K1 detect edge_index dtype (int64 vs int32)
//   K2 count in-degree over col (int atomics)
//   K3 dis[i] = deg^{-1/2}
//   K5 fill per-row buckets (col, norm packed as int2); bucket overflow
//      appends to a global overflow list (statistically never at mean deg 16)
//   K6 gather (FUSED with self-term): 1 warp per node, lane owns 4 features;
//      acc = (1+eps)*x[w] + sum over bucket of norm * x[col]; single write of
//      out. No separate init pass, no out re-read.
//   K7 drain overflow list with float atomics (no-op when empty).

#define N_MAX   100000
#define D       128
#define D4      (D / 4)        // 32 float4 per row
#define CAP     64
#define OVF_MAX 2000000

__device__ int   g_deg[N_MAX];                  // in-degree (col counts)
__device__ int   g_cnt[N_MAX];                  // per-row bucket fill counts
__device__ float g_dis[N_MAX];                  // deg^{-1/2}
__device__ int2  g_bkt[(size_t)N_MAX * CAP];    // bucket: {col, norm-bits}
__device__ int   g_is64;                        // edge dtype flag
__device__ int   g_ovf_n;                       // overflow entry count
__device__ int4  g_ovf[OVF_MAX];                // overflow: {row, col, norm-bits, 0}

// ---------------------------------------------------------------- edge access
__device__ __forceinline__ int edge_val(const void* ei, size_t idx, int is64) {
    if (is64) return (int)((const long long*)ei)[idx];
    return ((const int*)ei)[idx];
}

// ---------------------------------------------------------------- K0: zero
__global__ void k_zero(int n) {
    int i = blockIdx.x * blockDim.x + threadIdx.x;
    if (i < n) { g_deg[i] = 0; g_cnt[i] = 0; }
    if (i == 0) g_ovf_n = 0;
}

// ---------------------------------------------------------------- K1: detect
// int64 little-endian values < 2^31 -> every odd int32 word is 0.
// 64 odd words all zero from genuine int32 node-id data is ~impossible.
__global__ void k_detect(const void* ei) {
    if (threadIdx.x == 0 && blockIdx.x == 0) {
        const int* p = (const int*)ei;
        int nz = 0;
        #pragma unroll
        for (int k = 0; k < 64; k++) nz |= p[2 * k + 1];
        g_is64 = (nz == 0) ? 1 : 0;
    }
}

// ---------------------------------------------------------------- K2: degree
__global__ void k_count(const void* ei, int E) {
    int e = blockIdx.x * blockDim.x + threadIdx.x;
    if (e >= E) return;
    int is64 = g_is64;
    int c = edge_val(ei, (size_t)E + e, is64);
    atomicAdd(&g_deg[c], 1);
}

// ---------------------------------------------------------------- K3: dis
__global__ void k_dis(int n) {
    int i = blockIdx.x * blockDim.x + threadIdx.x;
    if (i >= n) return;
    int d = g_deg[i];
    g_dis[i] = (d > 0) ? rsqrtf((float)d) : 0.0f;
}

// ---------------------------------------------------------------- K5: fill
__global__ void k_fill(const void* ei, int E) {
    int e = blockIdx.x * blockDim.x + threadIdx.x;
    if (e >= E) return;
    int is64 = g_is64;
    int r = edge_val(ei, (size_t)e, is64);
    int c = edge_val(ei, (size_t)E + e, is64);
    float norm = g_dis[r] * g_dis[c];
    int slot = atomicAdd(&g_cnt[r], 1);
    if (slot < CAP) {
        g_bkt[(size_t)r * CAP + slot] = make_int2(c, __float_as_int(norm));
    } else {
        int o = atomicAdd(&g_ovf_n, 1);
        if (o < OVF_MAX)
            g_ovf[o] = make_int4(r, c, __float_as_int(norm), 0);
    }
}

// ---------------------------------------------------------------- K6: gather
// out[w] = (1+eps)*x[w] + sum_{bucket entries} norm * x[col] — fused, single
// write of out, no prior init.
__global__ void __launch_bounds__(256)
k_gather(const float4* __restrict__ x4, float4* __restrict__ o4,
         const float* __restrict__ eps, int n) {
    int w    = (blockIdx.x * blockDim.x + threadIdx.x) >> 5;
    int lane = threadIdx.x & 31;
    if (w >= n) return;

    int cnt = g_cnt[w];
    if (cnt > CAP) cnt = CAP;

    float  s  = 1.0f + eps[0];
    float4 xv = x4[(size_t)w * D4 + lane];
    float4 acc;
    acc.x = s * xv.x; acc.y = s * xv.y; acc.z = s * xv.z; acc.w = s * xv.w;

    size_t base = (size_t)w * CAP;
    for (int j0 = 0; j0 < cnt; j0 += 32) {
        int2 mine = make_int2(0, 0);
        int idx = j0 + lane;
        if (idx < cnt) mine = g_bkt[base + idx];
        int m = min(32, cnt - j0);

        #pragma unroll 4
        for (int j = 0; j < m; j++) {
            int   c  = __shfl_sync(0xffffffffu, mine.x, j);
            float nm = __int_as_float(__shfl_sync(0xffffffffu, mine.y, j));
            float4 v = x4[(size_t)c * D4 + lane];
            acc.x += nm * v.x;
            acc.y += nm * v.y;
            acc.z += nm * v.z;
            acc.w += nm * v.w;
        }
    }
    o4[(size_t)w * D4 + lane] = acc;
}

// ---------------------------------------------------------------- K7: overflow
// Persistent drain of overflow list into out (no-op for this distribution).
__global__ void k_ovf(const float4* __restrict__ x4, float* out) {
    int nov = g_ovf_n;
    if (nov > OVF_MAX) nov = OVF_MAX;
    int warp  = (blockIdx.x * blockDim.x + threadIdx.x) >> 5;
    int nwarp = (gridDim.x * blockDim.x) >> 5;
    int lane  = threadIdx.x & 31;
    for (int i = warp; i < nov; i += nwarp) {
        int4  t  = g_ovf[i];
        float nm = __int_as_float(t.z);
        float4 v = x4[(size_t)t.y * D4 + lane];
        float* o = out + (size_t)t.x * D + lane * 4;
        atomicAdd(o + 0, nm * v.x);
        atomicAdd(o + 1, nm * v.y);
        atomicAdd(o + 2, nm * v.z);
        atomicAdd(o + 3, nm * v.w);
    }
}

// ---------------------------------------------------------------- launch
extern "C" void kernel_launch(void* const* d_in, const int* in_sizes, int n_in,
                              void* d_out, int out_size) {
    const float* x   = (const float*)d_in[0];
    const float* eps = (const float*)d_in[1];
    const void*  ei  = d_in[2];
    float*       out = (float*)d_out;

    int n = in_sizes[0] / D;       // 100000
    int E = in_sizes[2] / 2;       // 1600000

    const int T = 256;
    k_zero  <<<(n + T - 1) / T, T>>>(n);
    k_detect<<<1, 32>>>(ei);
    k_count <<<(E + T - 1) / T, T>>>(ei, E);
    k_dis   <<<(n + T - 1) / T, T>>>(n);
    k_fill  <<<(E + T - 1) / T, T>>>(ei, E);
    k_gather<<<(n * 32 + T - 1) / T, T>>>((const float4*)x, (float4*)out, eps, n);
    k_ovf   <<<296, T>>>((const float4*)x, out);
}

// round 6
// speedup vs baseline: 1.2999x; 1.0181x over previous
#include <cuda_runtime.h>
#include <stdint.h>

// GINGCN forward:
//   deg[c]  = # edges with col==c  (in-degree over col)
//   dis[i]  = deg[i]>0 ? rsqrt(deg[i]) : 0
//   out[r]  = (1+eps)*x[r] + sum_{e: row[e]==r} dis[r]*dis[col[e]] * x[col[e]]
//
// Strategy: bucket-CSR gather, 5 launches.
//   K0 zero counters + overflow count + dtype detect (fused)
//   K2 count in-degree over col (int atomics)
//   K5 fill per-row buckets (col, norm packed as int2); norm computed inline
//      as rsqrt(deg[r]*deg[c]) — no separate dis pass. Bucket overflow
//      appends to a global overflow list (statistically never at mean deg 16)
//   K6 gather (fused self-term): 1 warp per node, lane owns 4 features;
//      acc = (1+eps)*x[w] + sum over bucket of norm * x[col]; single write.
//   K7 drain overflow list with float atomics (no-op when empty).

#define N_MAX   100000
#define D       128
#define D4      (D / 4)        // 32 float4 per row
#define CAP     64
#define OVF_MAX 2000000

__device__ int  g_deg[N_MAX];                  // in-degree (col counts)
__device__ int  g_cnt[N_MAX];                  // per-row bucket fill counts
__device__ int2 g_bkt[(size_t)N_MAX * CAP];    // bucket: {col, norm-bits}
__device__ int  g_is64;                        // edge dtype flag
__device__ int  g_ovf_n;                       // overflow entry count
__device__ int4 g_ovf[OVF_MAX];                // overflow: {row, col, norm-bits, 0}

// ---------------------------------------------------------------- edge access
__device__ __forceinline__ int edge_val(const void* ei, size_t idx, int is64) {
    if (is64) return (int)((const long long*)ei)[idx];
    return ((const int*)ei)[idx];
}

// ---------------------------------------------------------------- K0: zero+detect
// dtype sniff: int64 little-endian values < 2^31 -> every odd int32 word is 0.
// 64 odd words all zero from genuine int32 node-id data is ~impossible.
__global__ void k_zero(const void* ei, int n) {
    int i = blockIdx.x * blockDim.x + threadIdx.x;
    if (i < n) { g_deg[i] = 0; g_cnt[i] = 0; }
    if (i == 0) {
        g_ovf_n = 0;
        const int* p = (const int*)ei;
        int nz = 0;
        #pragma unroll
        for (int k = 0; k < 64; k++) nz |= p[2 * k + 1];
        g_is64 = (nz == 0) ? 1 : 0;
    }
}

// ---------------------------------------------------------------- K2: degree
__global__ void k_count(const void* ei, int E) {
    int e = blockIdx.x * blockDim.x + threadIdx.x;
    if (e >= E) return;
    int is64 = g_is64;
    int c = edge_val(ei, (size_t)E + e, is64);
    atomicAdd(&g_deg[c], 1);
}

// ---------------------------------------------------------------- K5: fill
// norm = dis[r]*dis[c] = rsqrt(deg[r]*deg[c]), 0 if either degree is 0.
__global__ void k_fill(const void* ei, int E) {
    int e = blockIdx.x * blockDim.x + threadIdx.x;
    if (e >= E) return;
    int is64 = g_is64;
    int r = edge_val(ei, (size_t)e, is64);
    int c = edge_val(ei, (size_t)E + e, is64);
    int dr = g_deg[r];
    int dc = g_deg[c];
    float norm = (dr > 0 && dc > 0) ? rsqrtf((float)dr * (float)dc) : 0.0f;
    int slot = atomicAdd(&g_cnt[r], 1);
    if (slot < CAP) {
        g_bkt[(size_t)r * CAP + slot] = make_int2(c, __float_as_int(norm));
    } else {
        int o = atomicAdd(&g_ovf_n, 1);
        if (o < OVF_MAX)
            g_ovf[o] = make_int4(r, c, __float_as_int(norm), 0);
    }
}

// ---------------------------------------------------------------- K6: gather
// out[w] = (1+eps)*x[w] + sum_{bucket entries} norm * x[col]
__global__ void __launch_bounds__(256)
k_gather(const float4* __restrict__ x4, float4* __restrict__ o4,
         const float* __restrict__ eps, int n) {
    int w    = (blockIdx.x * blockDim.x + threadIdx.x) >> 5;
    int lane = threadIdx.x & 31;
    if (w >= n) return;

    int cnt = g_cnt[w];
    if (cnt > CAP) cnt = CAP;

    float  s  = 1.0f + eps[0];
    float4 xv = x4[(size_t)w * D4 + lane];
    float4 acc;
    acc.x = s * xv.x; acc.y = s * xv.y; acc.z = s * xv.z; acc.w = s * xv.w;

    size_t base = (size_t)w * CAP;
    for (int j0 = 0; j0 < cnt; j0 += 32) {
        int2 mine = make_int2(0, 0);
        int idx = j0 + lane;
        if (idx < cnt) mine = g_bkt[base + idx];
        int m = min(32, cnt - j0);

        #pragma unroll 4
        for (int j = 0; j < m; j++) {
            int   c  = __shfl_sync(0xffffffffu, mine.x, j);
            float nm = __int_as_float(__shfl_sync(0xffffffffu, mine.y, j));
            float4 v = x4[(size_t)c * D4 + lane];
            acc.x += nm * v.x;
            acc.y += nm * v.y;
            acc.z += nm * v.z;
            acc.w += nm * v.w;
        }
    }
    o4[(size_t)w * D4 + lane] = acc;
}

// ---------------------------------------------------------------- K7: overflow
// Persistent drain of overflow list into out (no-op for this distribution).
__global__ void k_ovf(const float4* __restrict__ x4, float* out) {
    int nov = g_ovf_n;
    if (nov > OVF_MAX) nov = OVF_MAX;
    int warp  = (blockIdx.x * blockDim.x + threadIdx.x) >> 5;
    int nwarp = (gridDim.x * blockDim.x) >> 5;
    int lane  = threadIdx.x & 31;
    for (int i = warp; i < nov; i += nwarp) {
        int4  t  = g_ovf[i];
        float nm = __int_as_float(t.z);
        float4 v = x4[(size_t)t.y * D4 + lane];
        float* o = out + (size_t)t.x * D + lane * 4;
        atomicAdd(o + 0, nm * v.x);
        atomicAdd(o + 1, nm * v.y);
        atomicAdd(o + 2, nm * v.z);
        atomicAdd(o + 3, nm * v.w);
    }
}

// ---------------------------------------------------------------- launch
extern "C" void kernel_launch(void* const* d_in, const int* in_sizes, int n_in,
                              void* d_out, int out_size) {
    const float* x   = (const float*)d_in[0];
    const float* eps = (const float*)d_in[1];
    const void*  ei  = d_in[2];
    float*       out = (float*)d_out;

    int n = in_sizes[0] / D;       // 100000
    int E = in_sizes[2] / 2;       // 1600000

    const int T = 256;
    k_zero  <<<(n + T - 1) / T, T>>>(ei, n);
    k_count <<<(E + T - 1) / T, T>>>(ei, E);
    k_fill  <<<(E + T - 1) / T, T>>>(ei, E);
    k_gather<<<(n * 32 + T - 1) / T, T>>>((const float4*)x, (float4*)out, eps, n);
    k_ovf   <<<296, T>>>((const float4*)x, out);
}

// round 7
// speedup vs baseline: 1.4805x; 1.1389x over previous
#include <cuda_runtime.h>
#include <stdint.h>

// GINGCN forward:
//   deg[c]  = # edges with col==c  (in-degree over col)
//   dis[i]  = deg[i]>0 ? rsqrt(deg[i]) : 0
//   out[r]  = (1+eps)*x[r] + sum_{e: row[e]==r} dis[r]*dis[col[e]] * x[col[e]]
//
// Strategy: bucket-CSR gather, 4 launches.
//   K0 zero counters + overflow count + dtype detect (fused)
//   K1 ONE edge pass: atomicAdd deg[col]; append col to bucket[row]
//      (norm deferred — no deg reads here). Overflow -> global (r,c) list.
//   K2 gather: 1 warp/node, lane owns 4 features. Per 32-entry chunk each
//      lane loads its bucket col + deg[col], computes norm = dis_w*rsqrt(deg),
//      then warp broadcasts (col,norm) via shfl and gathers x[col] as float4.
//      acc starts at (1+eps)*x[w]; single out write.
//   K3 drain overflow list with float atomics (no-op when empty).

#define N_MAX   100000
#define D       128
#define D4      (D / 4)        // 32 float4 per row
#define CAP     64
#define OVF_MAX 2000000

__device__ int  g_deg[N_MAX];                  // in-degree (col counts)
__device__ int  g_cnt[N_MAX];                  // per-row bucket fill counts
__device__ int  g_bkt[(size_t)N_MAX * CAP];    // bucket: col only
__device__ int  g_is64;                        // edge dtype flag
__device__ int  g_ovf_n;                       // overflow entry count
__device__ int2 g_ovf[OVF_MAX];                // overflow: {row, col}

// ---------------------------------------------------------------- edge access
__device__ __forceinline__ int edge_val(const void* ei, size_t idx, int is64) {
    if (is64) return (int)((const long long*)ei)[idx];
    return ((const int*)ei)[idx];
}

// ---------------------------------------------------------------- K0: zero+detect
// dtype sniff: int64 little-endian values < 2^31 -> every odd int32 word is 0.
// 64 odd words all zero from genuine int32 node-id data is ~impossible.
__global__ void k_zero(const void* ei, int n) {
    int i = blockIdx.x * blockDim.x + threadIdx.x;
    if (i < n) { g_deg[i] = 0; g_cnt[i] = 0; }
    if (i == 0) {
        g_ovf_n = 0;
        const int* p = (const int*)ei;
        int nz = 0;
        #pragma unroll
        for (int k = 0; k < 64; k++) nz |= p[2 * k + 1];
        g_is64 = (nz == 0) ? 1 : 0;
    }
}

// ---------------------------------------------------------------- K1: count+fill
// Single pass: degree count and bucket append are independent, no deg reads.
__global__ void k_build(const void* ei, int E) {
    int e = blockIdx.x * blockDim.x + threadIdx.x;
    if (e >= E) return;
    int is64 = g_is64;
    int r = edge_val(ei, (size_t)e, is64);
    int c = edge_val(ei, (size_t)E + e, is64);
    atomicAdd(&g_deg[c], 1);
    int slot = atomicAdd(&g_cnt[r], 1);
    if (slot < CAP) {
        g_bkt[(size_t)r * CAP + slot] = c;
    } else {
        int o = atomicAdd(&g_ovf_n, 1);
        if (o < OVF_MAX) g_ovf[o] = make_int2(r, c);
    }
}

// ---------------------------------------------------------------- K2: gather
// out[w] = (1+eps)*x[w] + dis_w * sum rsqrt(deg[c]) * x[c]
// deg[c] >= 1 guaranteed for bucketed edges (the edge itself counted).
__global__ void __launch_bounds__(256)
k_gather(const float4* __restrict__ x4, float4* __restrict__ o4,
         const float* __restrict__ eps, int n) {
    int w    = (blockIdx.x * blockDim.x + threadIdx.x) >> 5;
    int lane = threadIdx.x & 31;
    if (w >= n) return;

    int cnt = g_cnt[w];
    if (cnt > CAP) cnt = CAP;

    float  s  = 1.0f + eps[0];
    float4 xv = x4[(size_t)w * D4 + lane];
    float4 acc;
    acc.x = s * xv.x; acc.y = s * xv.y; acc.z = s * xv.z; acc.w = s * xv.w;

    int   dw    = g_deg[w];
    float dis_w = (dw > 0) ? rsqrtf((float)dw) : 0.0f;

    size_t base = (size_t)w * CAP;
    for (int j0 = 0; j0 < cnt; j0 += 32) {
        int   mycol = 0;
        float mynrm = 0.0f;
        int idx = j0 + lane;
        if (idx < cnt) {
            mycol = g_bkt[base + idx];
            mynrm = dis_w * rsqrtf((float)g_deg[mycol]);
        }
        int m = min(32, cnt - j0);

        #pragma unroll 4
        for (int j = 0; j < m; j++) {
            int   c  = __shfl_sync(0xffffffffu, mycol, j);
            float nm = __shfl_sync(0xffffffffu, mynrm, j);
            float4 v = x4[(size_t)c * D4 + lane];
            acc.x += nm * v.x;
            acc.y += nm * v.y;
            acc.z += nm * v.z;
            acc.w += nm * v.w;
        }
    }
    o4[(size_t)w * D4 + lane] = acc;
}

// ---------------------------------------------------------------- K3: overflow
// Persistent drain of overflow list into out (no-op for this distribution).
// deg is final here; norm computed from deg directly.
__global__ void k_ovf(const float4* __restrict__ x4, float* out) {
    int nov = g_ovf_n;
    if (nov > OVF_MAX) nov = OVF_MAX;
    int warp  = (blockIdx.x * blockDim.x + threadIdx.x) >> 5;
    int nwarp = (gridDim.x * blockDim.x) >> 5;
    int lane  = threadIdx.x & 31;
    for (int i = warp; i < nov; i += nwarp) {
        int2 t = g_ovf[i];
        int dr = g_deg[t.x];
        int dc = g_deg[t.y];
        float nm = (dr > 0 && dc > 0) ? rsqrtf((float)dr * (float)dc) : 0.0f;
        float4 v = x4[(size_t)t.y * D4 + lane];
        float* o = out + (size_t)t.x * D + lane * 4;
        atomicAdd(o + 0, nm * v.x);
        atomicAdd(o + 1, nm * v.y);
        atomicAdd(o + 2, nm * v.z);
        atomicAdd(o + 3, nm * v.w);
    }
}

// ---------------------------------------------------------------- launch
extern "C" void kernel_launch(void* const* d_in, const int* in_sizes, int n_in,
                              void* d_out, int out_size) {
    const float* x   = (const float*)d_in[0];
    const float* eps = (const float*)d_in[1];
    const void*  ei  = d_in[2];
    float*       out = (float*)d_out;

    int n = in_sizes[0] / D;       // 100000
    int E = in_sizes[2] / 2;       // 1600000

    const int T = 256;
    k_zero  <<<(n + T - 1) / T, T>>>(ei, n);
    k_build <<<(E + T - 1) / T, T>>>(ei, E);
    k_gather<<<(n * 32 + T - 1) / T, T>>>((const float4*)x, (float4*)out, eps, n);
    k_ovf   <<<296, T>>>((const float4*)x, out);
}